// round 11
// baseline (speedup 1.0000x reference)
#include <cuda_runtime.h>

#define OUTB 7
#define NBINS 49
#define NCH 256
#define FH 50
#define FW 50
#define NPOS (FH * FW)        // 2500 positions per batch image
#define NROI 256
#define NEGV (-3e38f)
#define TILE_MAX 19           // Lh, Lw <= 19 for valid inputs (clamped)
#define PPAD 5120             // padded position count (defensive)
#define STG_STRIDE 65         // staging row stride (odd => conflict-light)
#define CH2 (NCH / 2)         // float2 stride per position

// Channel-last copy of features: g_featT[(b*2500 + h*50 + w) * 256 + c].
__device__ float g_featT[PPAD * NCH];

// ---- Kernel 1: transpose (b,c,h,w) -> (pos, c), both sides coalesced ----
__global__ void __launch_bounds__(256)
transpose_kernel(const float* __restrict__ feat) {
    __shared__ float t[32][33];
    const int p0 = blockIdx.x * 32;
    const int c0 = blockIdx.y * 32;
    const int b  = blockIdx.z;
    const int tx = threadIdx.x;           // 32
    const int ty = threadIdx.y;           // 8

    #pragma unroll
    for (int dy = 0; dy < 4; dy++) {
        const int c = c0 + ty * 4 + dy;
        const int p = p0 + tx;
        float v = 0.0f;
        if (p < NPOS) v = __ldg(feat + ((size_t)(b * NCH + c)) * NPOS + p);
        t[ty * 4 + dy][tx] = v;
    }
    __syncthreads();
    #pragma unroll
    for (int dy = 0; dy < 4; dy++) {
        const int p = p0 + ty * 4 + dy;
        const int c = c0 + tx;
        if (p < NPOS)
            g_featT[((size_t)(b * NPOS + p)) * NCH + c] = t[tx][ty * 4 + dy];
    }
}

// ---- Kernel 2: pool from channel-last global ----
// Block = (roi, 64-ch chunk), 8 warps; warp owns bins warp, warp+8, ...
// Per bin: 4 column-max accumulators; rows gated warp-uniform, columns
// load-predicated warp-uniform (off-columns stay NEG => final max unconditional).
__global__ void __launch_bounds__(256)
roipool_kernel(const float* __restrict__ rois,
               const int* __restrict__ raw,
               float* __restrict__ out) {
    __shared__ unsigned int binsS[NBINS];
    __shared__ float staging[NBINS * STG_STRIDE];   // [bin][ch], 12.7 KB

    const int tid  = threadIdx.x;
    const int warp = tid >> 5;
    const int lane = tid & 31;
    const int r  = blockIdx.x >> 2;       // 4 chunks per roi
    const int c0 = (blockIdx.x & 3) * 64;

    // Geometry (redundant per thread). Reference semantics: ri = int32(roi/16)
    // (fp32 mul, trunc); h-bounds from x coords, w-bounds from y coords.
    const float4 rv = __ldg(((const float4*)rois) + r);
    int x1 = (int)(rv.x * 0.0625f);
    int y1 = (int)(rv.y * 0.0625f);
    int x2 = (int)(rv.z * 0.0625f);
    int y2 = (int)(rv.w * 0.0625f);
    int Lh = x2 - x1;
    int Lw = y2 - y1;
    if (Lh < 0) Lh = 0; else if (Lh > TILE_MAX) Lh = TILE_MAX;
    if (Lw < 0) Lw = 0; else if (Lw > TILE_MAX) Lw = TILE_MAX;

    // Bin descriptors: image-pos of window start, wh<=4, wn<=4.
    if (tid < NBINS) {
        const int ph = tid / OUTB;
        const int pw = tid - ph * OUTB;
        const int hs = (ph * Lh) / OUTB;
        const int he = ((ph + 1) * Lh + OUTB - 1) / OUTB;
        const int ws = (pw * Lw) / OUTB;
        const int we = ((pw + 1) * Lw + OUTB - 1) / OUTB;
        binsS[tid] = (unsigned int)((x1 + hs) * FW + (y1 + ws))
                   | ((unsigned int)(he - hs) << 16)
                   | ((unsigned int)(we - ws) << 20);
    }

    // int64-vs-int32 roi_indices detection: int64 LE values in {0,1} => all
    // odd int32 words zero (prob ~2^-128 for random int32 {0,1} data).
    const int myok = (tid < NROI / 2) ? (raw[2 * tid + 1] == 0) : 1;
    const int is64 = __syncthreads_and(myok);     // also publishes binsS
    const int b = is64 ? raw[2 * r] : raw[r];

    const float2* fT = (const float2*)g_featT;
    const int chBase = (c0 >> 1) + lane;
    const float2 nf2 = make_float2(NEGV, NEGV);

    for (int bb = warp; bb < NBINS; bb += 8) {
        const unsigned int e = binsS[bb];
        const int wh = (e >> 16) & 0xF;
        const int wn = e >> 20;
        const float2* p = fT + ((size_t)(b * NPOS + (int)(e & 0xFFFF))) * CH2
                        + chBase;

        // 8 independent max chains (4 cols x float2); loads of different rows
        // are independent => scheduler overlaps them (MLP kept from R10).
        float2 m0 = nf2, m1 = nf2, m2 = nf2, m3 = nf2;
        #pragma unroll
        for (int i = 0; i < 4; i++) {
            if (i < wh) {                             // warp-uniform row gate
                const float2* q = p + i * (FW * CH2);
                float2 a0 = __ldg(q);                 // wn >= 1 always
                float2 a1 = (wn > 1) ? __ldg(q + CH2)     : nf2;  // @P LDG
                float2 a2 = (wn > 2) ? __ldg(q + 2 * CH2) : nf2;
                float2 a3 = (wn > 3) ? __ldg(q + 3 * CH2) : nf2;
                m0.x = fmaxf(m0.x, a0.x);  m0.y = fmaxf(m0.y, a0.y);
                m1.x = fmaxf(m1.x, a1.x);  m1.y = fmaxf(m1.y, a1.y);
                m2.x = fmaxf(m2.x, a2.x);  m2.y = fmaxf(m2.y, a2.y);
                m3.x = fmaxf(m3.x, a3.x);  m3.y = fmaxf(m3.y, a3.y);
            }
        }
        // Off columns never loaded => still NEG => unconditional reduction.
        float2 m;
        m.x = fmaxf(fmaxf(m0.x, m1.x), fmaxf(m2.x, m3.x));
        m.y = fmaxf(fmaxf(m0.y, m1.y), fmaxf(m2.y, m3.y));

        staging[bb * STG_STRIDE + 2 * lane]     = m.x;
        staging[bb * STG_STRIDE + 2 * lane + 1] = m.y;
    }
    __syncthreads();

    // ---- Coalesced output: 3136 contiguous floats for (r, c0..c0+63) ----
    float* o = out + ((size_t)r * NCH + c0) * NBINS;
    for (int k = tid; k < 64 * NBINS; k += 256) {
        const int ch = k / NBINS;                     // const div -> mul.hi
        const int bbq = k - ch * NBINS;
        o[k] = staging[bbq * STG_STRIDE + ch];
    }
}

extern "C" void kernel_launch(void* const* d_in, const int* in_sizes, int n_in,
                              void* d_out, int out_size) {
    const float* features = (const float*)d_in[0];
    const float* rois     = (const float*)d_in[1];
    const int*   roi_idx  = (const int*)d_in[2];  // width detected at runtime
    float* out = (float*)d_out;

    dim3 tgrid((NPOS + 31) / 32, NCH / 32, 2);    // 79 x 8 x 2
    transpose_kernel<<<tgrid, dim3(32, 8)>>>(features);

    roipool_kernel<<<NROI * 4, 256>>>(rois, roi_idx, out);
}

// round 12
// speedup vs baseline: 1.1122x; 1.1122x over previous
#include <cuda_runtime.h>

#define OUTB 7
#define NBINS 49
#define NCH 256
#define FH 50
#define FW 50
#define NPOS (FH * FW)        // 2500 positions per batch image
#define NROI 256
#define NEGV (-3e38f)
#define TILE_MAX 19           // Lh, Lw <= 19 for valid inputs (clamped)
#define PPAD 5120             // padded position count (defensive)
#define CH4 (NCH / 4)         // float4 stride per position (64)
#define STG_W 33              // staging row stride in float4 (odd => LDS conflict-free)

// Channel-last copy of features: g_featT[(b*2500 + h*50 + w) * 256 + c].
__device__ float g_featT[PPAD * NCH];

// ---- Kernel 1: transpose (b,c,h,w) -> (pos, c), both sides coalesced ----
__global__ void __launch_bounds__(256)
transpose_kernel(const float* __restrict__ feat) {
    __shared__ float t[32][33];
    const int p0 = blockIdx.x * 32;
    const int c0 = blockIdx.y * 32;
    const int b  = blockIdx.z;
    const int tx = threadIdx.x;           // 32
    const int ty = threadIdx.y;           // 8

    #pragma unroll
    for (int dy = 0; dy < 4; dy++) {
        const int c = c0 + ty * 4 + dy;
        const int p = p0 + tx;
        float v = 0.0f;
        if (p < NPOS) v = __ldg(feat + ((size_t)(b * NCH + c)) * NPOS + p);
        t[ty * 4 + dy][tx] = v;
    }
    __syncthreads();
    #pragma unroll
    for (int dy = 0; dy < 4; dy++) {
        const int p = p0 + ty * 4 + dy;
        const int c = c0 + tx;
        if (p < NPOS)
            g_featT[((size_t)(b * NPOS + p)) * NCH + c] = t[tx][ty * 4 + dy];
    }
}

__device__ __forceinline__ void fmax4(float4& m, const float4 a) {
    m.x = fmaxf(m.x, a.x);
    m.y = fmaxf(m.y, a.y);
    m.z = fmaxf(m.z, a.z);
    m.w = fmaxf(m.w, a.w);
}

// ---- Kernel 2: pool from channel-last global, float4 per lane ----
// Block = (roi, 128-ch half), 8 warps; warp covers 128 channels per bin-walk
// and owns bins warp, warp+8, ...  Per-bin overhead amortized over 128 outputs.
__global__ void __launch_bounds__(256, 4)
roipool_kernel(const float* __restrict__ rois,
               const int* __restrict__ raw,
               float* __restrict__ out) {
    __shared__ unsigned int binsS[NBINS];
    __shared__ float4 staging4[NBINS * STG_W];    // [bin][c4], 25.9 KB

    const int tid  = threadIdx.x;
    const int warp = tid >> 5;
    const int lane = tid & 31;
    const int r  = blockIdx.x >> 1;       // 2 chunks per roi
    const int c0 = (blockIdx.x & 1) * 128;

    // Geometry (redundant per thread). Reference semantics: ri = int32(roi/16)
    // (fp32 mul, trunc); h-bounds from x coords, w-bounds from y coords.
    const float4 rv = __ldg(((const float4*)rois) + r);
    int x1 = (int)(rv.x * 0.0625f);
    int y1 = (int)(rv.y * 0.0625f);
    int x2 = (int)(rv.z * 0.0625f);
    int y2 = (int)(rv.w * 0.0625f);
    int Lh = x2 - x1;
    int Lw = y2 - y1;
    if (Lh < 0) Lh = 0; else if (Lh > TILE_MAX) Lh = TILE_MAX;
    if (Lw < 0) Lw = 0; else if (Lw > TILE_MAX) Lw = TILE_MAX;

    // Bin descriptors: image-pos of window start, wh<=4, wn<=4.
    if (tid < NBINS) {
        const int ph = tid / OUTB;
        const int pw = tid - ph * OUTB;
        const int hs = (ph * Lh) / OUTB;
        const int he = ((ph + 1) * Lh + OUTB - 1) / OUTB;
        const int ws = (pw * Lw) / OUTB;
        const int we = ((pw + 1) * Lw + OUTB - 1) / OUTB;
        binsS[tid] = (unsigned int)((x1 + hs) * FW + (y1 + ws))
                   | ((unsigned int)(he - hs) << 16)
                   | ((unsigned int)(we - ws) << 20);
    }

    // int64-vs-int32 roi_indices detection: int64 LE values in {0,1} => all
    // odd int32 words zero (prob ~2^-128 for random int32 {0,1} data).
    const int myok = (tid < NROI / 2) ? (raw[2 * tid + 1] == 0) : 1;
    const int is64 = __syncthreads_and(myok);     // also publishes binsS
    const int b = is64 ? raw[2 * r] : raw[r];

    const float4* fT = (const float4*)g_featT;
    const int chBase = (c0 >> 2) + lane;          // float4 index of lane's channels
    const float4 nf4 = make_float4(NEGV, NEGV, NEGV, NEGV);

    for (int bb = warp; bb < NBINS; bb += 8) {
        const unsigned int e = binsS[bb];
        const int wh = (e >> 16) & 0xF;
        const int wn = e >> 20;
        const float4* p = fT + ((size_t)(b * NPOS + (int)(e & 0xFFFF))) * CH4
                        + chBase;

        // 4 column accumulators; rows gated warp-uniform, columns predicated
        // warp-uniform (off columns stay NEG => final reduce unconditional).
        // All in-window loads are in-bounds by construction (h<=x2-1<=48,
        // w<=y2-1<=49).
        float4 m0 = nf4, m1 = nf4, m2 = nf4, m3 = nf4;
        #pragma unroll
        for (int i = 0; i < 4; i++) {
            if (i < wh) {
                const float4* q = p + i * (FW * CH4);
                float4 a0 = __ldg(q);                          // wn >= 1 always
                float4 a1 = (wn > 1) ? __ldg(q + CH4)     : nf4;
                float4 a2 = (wn > 2) ? __ldg(q + 2 * CH4) : nf4;
                float4 a3 = (wn > 3) ? __ldg(q + 3 * CH4) : nf4;
                fmax4(m0, a0);
                fmax4(m1, a1);
                fmax4(m2, a2);
                fmax4(m3, a3);
            }
        }
        fmax4(m0, m1);
        fmax4(m2, m3);
        fmax4(m0, m2);

        staging4[bb * STG_W + lane] = m0;    // STS.128, lane-stride 1: clean
    }
    __syncthreads();

    // ---- Coalesced output: 128*49 floats for (r, c0..c0+127) ----
    // Element s = c4*49 + bb: LDS.128 at lane-stride 33 (odd => conflict-free),
    // then 4 STG.32 into runs of 49 consecutive floats (coalesced).
    float* o = out + ((size_t)r * NCH + c0) * NBINS;
    for (int s = tid; s < 32 * NBINS; s += 256) {
        const int c4 = s / NBINS;                 // const div -> mul.hi
        const int bbq = s - c4 * NBINS;
        const float4 m = staging4[bbq * STG_W + c4];
        float* po = o + 4 * c4 * NBINS + bbq;
        po[0]         = m.x;
        po[NBINS]     = m.y;
        po[2 * NBINS] = m.z;
        po[3 * NBINS] = m.w;
    }
}

extern "C" void kernel_launch(void* const* d_in, const int* in_sizes, int n_in,
                              void* d_out, int out_size) {
    const float* features = (const float*)d_in[0];
    const float* rois     = (const float*)d_in[1];
    const int*   roi_idx  = (const int*)d_in[2];  // width detected at runtime
    float* out = (float*)d_out;

    dim3 tgrid((NPOS + 31) / 32, NCH / 32, 2);    // 79 x 8 x 2
    transpose_kernel<<<tgrid, dim3(32, 8)>>>(features);

    roipool_kernel<<<NROI * 2, 256>>>(rois, roi_idx, out);
}